// round 11
// baseline (speedup 1.0000x reference)
#include <cuda_runtime.h>
#include <math.h>

#define Nn 8192
#define Kk 64
#define Dd 512
#define FD 2048   // 4*D

typedef unsigned long long u64t;

// ---- packed f32x2 ops (Blackwell FFMA2; each half = independent IEEE rn FMA) ----
#define PACKF2(d, lo, hi)  asm("mov.b64 %0, {%1, %2};" : "=l"(d) : "f"(lo), "f"(hi))
#define UNPACKF2(lo, hi, s) asm("mov.b64 {%0, %1}, %2;" : "=f"(lo), "=f"(hi) : "l"(s))
#define FMA2(d, a, b, c)   asm("fma.rn.f32x2 %0, %1, %2, %3;" : "=l"(d) : "l"(a), "l"(b), "l"(c))

// Scratch (allocation-free device globals)
__device__ float g_P[(size_t)Nn * FD];      // 64 MB: partial chain f@W_L^T (no biases)
__device__ float g_hw[(size_t)Nn * FD];     // 64 MB: h@W_hh^T per step
__device__ float g_h[2][(size_t)Nn * Dd];   // ping/pong h
__device__ float g_c[(size_t)Nn * Dd];      // cell state
__device__ float g_r[(size_t)Nn * Dd];      // r = a @ G

// ---- XLA EmitFastTanh f32 (verbatim) ----
__device__ __forceinline__ float tanh_xla(float x) {
    float ax = fabsf(x);
    float xc = fminf(fmaxf(x, -7.90531110763549805f), 7.90531110763549805f);
    float x2 = __fmul_rn(xc, xc);
    float p = -2.76076847742355e-16f;
    p = __fadd_rn(__fmul_rn(p, x2), 2.00018790482477e-13f);
    p = __fadd_rn(__fmul_rn(p, x2), -8.60467152213735e-11f);
    p = __fadd_rn(__fmul_rn(p, x2), 5.12229709037114e-08f);
    p = __fadd_rn(__fmul_rn(p, x2), 1.48572235717979e-05f);
    p = __fadd_rn(__fmul_rn(p, x2), 6.37261928875436e-04f);
    p = __fadd_rn(__fmul_rn(p, x2), 4.89352455891786e-03f);
    float num = __fmul_rn(xc, p);
    float q = 1.19825839466702e-06f;
    q = __fadd_rn(__fmul_rn(q, x2), 1.18534705686654e-04f);
    q = __fadd_rn(__fmul_rn(q, x2), 2.26843463243900e-03f);
    q = __fadd_rn(__fmul_rn(q, x2), 4.89352518554385e-03f);
    float r = __fdiv_rn(num, q);
    return (ax < 0.0004f) ? x : r;
}
__device__ __forceinline__ float sig_xla(float x) {
    return __fadd_rn(0.5f, __fmul_rn(0.5f, tanh_xla(__fmul_rn(0.5f, x))));
}

// ---------------- init: h0 = f, c = 0 ----------------
__global__ void k_init(const float* __restrict__ f) {
    int i = blockIdx.x * 256 + threadIdx.x;
    g_h[0][i] = f[i];
    g_c[i] = 0.f;
}

// Shared-memory overlay: gemm path 8192+16384=24576 B; attnr path 41216 B
#define SU_BYTES 41216

// ---- fused attention + r body: one CTA = 32 rows (rb in 0..255), verbatim R10 ----
__device__ __forceinline__ void attnr_body(char* su, int rb, const float* __restrict__ h,
                                           const float* __restrict__ G) {
    float* Gs = reinterpret_cast<float*>(su);                          // [64*129]
    float (*a2)[Kk] = reinterpret_cast<float(*)[Kk]>(su + Kk * 129 * 4);  // [32][64]
    const int tid = threadIdx.x;
    const int warp = tid >> 5, lane = tid & 31;
    const int n0 = rb * 32 + warp * 4;

    float acc[4][2];
#pragma unroll
    for (int r = 0; r < 4; r++) { acc[r][0] = 0.f; acc[r][1] = 0.f; }
    for (int ch = 0; ch < 4; ch++) {
        __syncthreads();
        for (int e = tid; e < Kk * 128; e += 256)
            Gs[(e >> 7) * 129 + (e & 127)] = G[(e >> 7) * Dd + ch * 128 + (e & 127)];
        __syncthreads();
#pragma unroll 2
        for (int d = 0; d < 128; d++) {
            float w0 = Gs[lane * 129 + d];
            float w1 = Gs[(lane + 32) * 129 + d];
#pragma unroll
            for (int r = 0; r < 4; r++) {
                float hv = h[(size_t)(n0 + r) * Dd + ch * 128 + d];
                acc[r][0] = fmaf(hv, w0, acc[r][0]);
                acc[r][1] = fmaf(hv, w1, acc[r][1]);
            }
        }
    }
#pragma unroll
    for (int r = 0; r < 4; r++) {
        float m = fmaxf(acc[r][0], acc[r][1]);
#pragma unroll
        for (int off = 16; off; off >>= 1) m = fmaxf(m, __shfl_xor_sync(0xffffffffu, m, off));
        float e0 = expf(acc[r][0] - m);
        float e1 = expf(acc[r][1] - m);
        float s = __fadd_rn(e0, e1);
#pragma unroll
        for (int off = 16; off; off >>= 1) s = __fadd_rn(s, __shfl_xor_sync(0xffffffffu, s, off));
        s = __shfl_sync(0xffffffffu, s, 0);
        a2[warp * 4 + r][lane]      = __fdiv_rn(e0, s);
        a2[warp * 4 + r][lane + 32] = __fdiv_rn(e1, s);
    }
    __syncthreads();

    float (*Gr)[128] = reinterpret_cast<float(*)[128]>(su);
    const int dthr = tid & 31, rgrp = tid >> 5;
    for (int ch = 0; ch < 4; ch++) {
        for (int e = tid; e < Kk * 128; e += 256)
            Gr[e >> 7][e & 127] = G[(size_t)(e >> 7) * Dd + ch * 128 + (e & 127)];
        __syncthreads();
        u64t acc2[4][2];
#pragma unroll
        for (int r = 0; r < 4; r++) { acc2[r][0] = 0ull; acc2[r][1] = 0ull; }
        for (int k = 0; k < Kk; k++) {
            u64t g2[2];
            *(uint4*)&g2[0] = *(const uint4*)&Gr[k][dthr * 4];
#pragma unroll
            for (int r = 0; r < 4; r++) {
                float av = a2[rgrp * 4 + r][k];
                u64t av2;
                PACKF2(av2, av, av);
                FMA2(acc2[r][0], av2, g2[0], acc2[r][0]);
                FMA2(acc2[r][1], av2, g2[1], acc2[r][1]);
            }
        }
#pragma unroll
        for (int r = 0; r < 4; r++) {
            float x0, x1, x2, x3;
            UNPACKF2(x0, x1, acc2[r][0]);
            UNPACKF2(x2, x3, acc2[r][1]);
            *(float4*)&g_r[(size_t)(rb * 32 + rgrp * 4 + r) * Dd + ch * 128 + dthr * 4] =
                make_float4(x0, x1, x2, x3);
        }
        __syncthreads();
    }
}

// ---------------- merged launch: 64x128 gemm tiles + attnr CTAs ----------------
// G != null: grid (18, 128); x<2 -> attnr (rb = y*2+x), x>=2 -> gemm tile jb=(x-2)*128.
// G == null: pure gemm, grid (16, 128), jb = x*128 (P precompute).
__global__ __launch_bounds__(256, 3) void k_gemm(const float* __restrict__ Aopt, int cur,
                                                 const float* __restrict__ B, long bstride,
                                                 float* __restrict__ C,
                                                 const float* __restrict__ G) {
    __shared__ __align__(16) char su[SU_BYTES];
    const float* __restrict__ A = Aopt ? Aopt : g_h[cur];
    int jb;
    if (G) {
        if (blockIdx.x < 2) { attnr_body(su, blockIdx.y * 2 + blockIdx.x, A, G); return; }
        jb = (blockIdx.x - 2) * 128;
    } else {
        jb = blockIdx.x * 128;
    }
    float (*As)[16][64]  = reinterpret_cast<float(*)[16][64]>(su);           // 8 KB
    float (*Bs)[16][128] = reinterpret_cast<float(*)[16][128]>(su + 8192);   // 16 KB
    const int mb = blockIdx.y * 64;
    const int tid = threadIdx.x, tx = tid & 15, ty = tid >> 4;
    const int lra = tid >> 2, lka = (tid & 3) << 2;    // A: 64 rows x 4 k-floats
    const int lrb = tid >> 1, lkb = (tid & 1) << 3;    // B: 128 rows x 8 k-floats
    u64t acc2[4][4];
#pragma unroll
    for (int i = 0; i < 4; i++)
#pragma unroll
        for (int q = 0; q < 4; q++) acc2[i][q] = 0ull;

    const float* Arow = A + (size_t)(mb + lra) * Dd + lka;
    const float* Brow = B + (size_t)(jb + lrb) * bstride + lkb;

    float4 av = *(const float4*)(Arow);
    float4 b0 = *(const float4*)(Brow), b1 = *(const float4*)(Brow + 4);
    As[0][lka + 0][lra] = av.x; As[0][lka + 1][lra] = av.y; As[0][lka + 2][lra] = av.z; As[0][lka + 3][lra] = av.w;
    Bs[0][lkb + 0][lrb] = b0.x; Bs[0][lkb + 1][lrb] = b0.y; Bs[0][lkb + 2][lrb] = b0.z; Bs[0][lkb + 3][lrb] = b0.w;
    Bs[0][lkb + 4][lrb] = b1.x; Bs[0][lkb + 5][lrb] = b1.y; Bs[0][lkb + 6][lrb] = b1.z; Bs[0][lkb + 7][lrb] = b1.w;
    __syncthreads();

    for (int kt = 0; kt < 32; kt++) {
        const int buf = kt & 1;
        if (kt < 31) {
            av = *(const float4*)(Arow + (kt + 1) * 16);
            b0 = *(const float4*)(Brow + (kt + 1) * 16);
            b1 = *(const float4*)(Brow + (kt + 1) * 16 + 4);
        }
#pragma unroll
        for (int k = 0; k < 16; k++) {
            float ar[4];
            *(float4*)&ar[0] = *(const float4*)&As[buf][k][ty * 4];
            u64t ap[4], bp[4];
#pragma unroll
            for (int i = 0; i < 4; i++) PACKF2(ap[i], ar[i], ar[i]);
            *(uint4*)&bp[0] = *(const uint4*)&Bs[buf][k][tx * 4];
            *(uint4*)&bp[2] = *(const uint4*)&Bs[buf][k][64 + tx * 4];
#pragma unroll
            for (int i = 0; i < 4; i++)
#pragma unroll
                for (int q = 0; q < 4; q++) FMA2(acc2[i][q], ap[i], bp[q], acc2[i][q]);
        }
        if (kt < 31) {
            const int nb = buf ^ 1;
            As[nb][lka + 0][lra] = av.x; As[nb][lka + 1][lra] = av.y; As[nb][lka + 2][lra] = av.z; As[nb][lka + 3][lra] = av.w;
            Bs[nb][lkb + 0][lrb] = b0.x; Bs[nb][lkb + 1][lrb] = b0.y; Bs[nb][lkb + 2][lrb] = b0.z; Bs[nb][lkb + 3][lrb] = b0.w;
            Bs[nb][lkb + 4][lrb] = b1.x; Bs[nb][lkb + 5][lrb] = b1.y; Bs[nb][lkb + 6][lrb] = b1.z; Bs[nb][lkb + 7][lrb] = b1.w;
            __syncthreads();
        }
    }
#pragma unroll
    for (int i = 0; i < 4; i++) {
        int n = mb + ty * 4 + i;
#pragma unroll
        for (int q = 0; q < 2; q++) {
            float lo, hi;
            UNPACKF2(lo, hi, acc2[i][q]);
            *(float2*)&C[(size_t)n * FD + jb + tx * 4 + q * 2] = make_float2(lo, hi);
        }
#pragma unroll
        for (int q = 2; q < 4; q++) {
            float lo, hi;
            UNPACKF2(lo, hi, acc2[i][q]);
            *(float2*)&C[(size_t)n * FD + jb + 64 + tx * 4 + (q - 2) * 2] = make_float2(lo, hi);
        }
    }
}

// ---------------- x-chain GEMM (resumed from g_P), 64x128 tile + fused LSTM ----------------
__global__ __launch_bounds__(256, 3) void k_gx(int cur, const float* __restrict__ Wih,
        const float* __restrict__ bih, const float* __restrict__ bhh,
        const float* __restrict__ f, float* __restrict__ dout, int last) {
    __shared__ float As[2][16][64];
    __shared__ float Bs[2][16][128];
    float* __restrict__ hout = last ? dout : g_h[cur ^ 1];
    const int dcb = blockIdx.x * 32, mb = blockIdx.y * 64;
    const int tid = threadIdx.x, tx = tid & 15, ty = tid >> 4;
    const int lra = tid >> 2, lka = (tid & 3) << 2;
    const int lrb = tid >> 1, lkb = (tid & 1) << 3;
    const size_t bj = (size_t)((lrb >> 5) * Dd + dcb + (lrb & 31));

    const float* Arow = g_r + (size_t)(mb + lra) * Dd + lka;
    const float* Brow = Wih + bj * 1024 + 512 + lkb;

    u64t acc2[4][4];
#pragma unroll
    for (int i = 0; i < 4; i++) {
        int n = mb + ty * 4 + i;
#pragma unroll
        for (int g = 0; g < 4; g++) {
            float2 v = *(const float2*)&g_P[(size_t)n * FD + g * Dd + dcb + tx * 2];
            PACKF2(acc2[i][g], v.x, v.y);
        }
    }

    float4 av = *(const float4*)(Arow);
    float4 b0 = *(const float4*)(Brow), b1 = *(const float4*)(Brow + 4);
    As[0][lka + 0][lra] = av.x; As[0][lka + 1][lra] = av.y; As[0][lka + 2][lra] = av.z; As[0][lka + 3][lra] = av.w;
    Bs[0][lkb + 0][lrb] = b0.x; Bs[0][lkb + 1][lrb] = b0.y; Bs[0][lkb + 2][lrb] = b0.z; Bs[0][lkb + 3][lrb] = b0.w;
    Bs[0][lkb + 4][lrb] = b1.x; Bs[0][lkb + 5][lrb] = b1.y; Bs[0][lkb + 6][lrb] = b1.z; Bs[0][lkb + 7][lrb] = b1.w;
    __syncthreads();

    for (int kt = 0; kt < 32; kt++) {
        const int buf = kt & 1;
        if (kt < 31) {
            av = *(const float4*)(Arow + (kt + 1) * 16);
            b0 = *(const float4*)(Brow + (kt + 1) * 16);
            b1 = *(const float4*)(Brow + (kt + 1) * 16 + 4);
        }
#pragma unroll
        for (int k = 0; k < 16; k++) {
            float ar[4];
            *(float4*)&ar[0] = *(const float4*)&As[buf][k][ty * 4];
            u64t ap[4], bp[4];
#pragma unroll
            for (int i = 0; i < 4; i++) PACKF2(ap[i], ar[i], ar[i]);
#pragma unroll
            for (int g = 0; g < 4; g++)
                bp[g] = *(const u64t*)&Bs[buf][k][g * 32 + tx * 2];
#pragma unroll
            for (int i = 0; i < 4; i++)
#pragma unroll
                for (int g = 0; g < 4; g++) FMA2(acc2[i][g], ap[i], bp[g], acc2[i][g]);
        }
        if (kt < 31) {
            const int nb = buf ^ 1;
            As[nb][lka + 0][lra] = av.x; As[nb][lka + 1][lra] = av.y; As[nb][lka + 2][lra] = av.z; As[nb][lka + 3][lra] = av.w;
            Bs[nb][lkb + 0][lrb] = b0.x; Bs[nb][lkb + 1][lrb] = b0.y; Bs[nb][lkb + 2][lrb] = b0.z; Bs[nb][lkb + 3][lrb] = b0.w;
            Bs[nb][lkb + 4][lrb] = b1.x; Bs[nb][lkb + 5][lrb] = b1.y; Bs[nb][lkb + 6][lrb] = b1.z; Bs[nb][lkb + 7][lrb] = b1.w;
            __syncthreads();
        }
    }

    // epilogue: ((x + b_ih) + hW) + b_hh, XLA pointwise (identical), write c / h
#pragma unroll
    for (int i = 0; i < 4; i++) {
        int n = mb + ty * 4 + i;
        const float* hwp = &g_hw[(size_t)n * FD];
        float ax[8];
#pragma unroll
        for (int g = 0; g < 4; g++) UNPACKF2(ax[g * 2], ax[g * 2 + 1], acc2[i][g]);
#pragma unroll
        for (int p = 0; p < 2; p++) {
            int dc = dcb + tx * 2 + p;
            float iv = __fadd_rn(__fadd_rn(__fadd_rn(ax[0 + p], bih[0 * Dd + dc]), hwp[0 * Dd + dc]), bhh[0 * Dd + dc]);
            float fv = __fadd_rn(__fadd_rn(__fadd_rn(ax[2 + p], bih[1 * Dd + dc]), hwp[1 * Dd + dc]), bhh[1 * Dd + dc]);
            float gv = __fadd_rn(__fadd_rn(__fadd_rn(ax[4 + p], bih[2 * Dd + dc]), hwp[2 * Dd + dc]), bhh[2 * Dd + dc]);
            float ov = __fadd_rn(__fadd_rn(__fadd_rn(ax[6 + p], bih[3 * Dd + dc]), hwp[3 * Dd + dc]), bhh[3 * Dd + dc]);
            float co = g_c[(size_t)n * Dd + dc];
            float cn = __fadd_rn(__fmul_rn(sig_xla(fv), co), __fmul_rn(sig_xla(iv), tanh_xla(gv)));
            float hn = __fadd_rn(__fmul_rn(sig_xla(ov), tanh_xla(cn)), f[(size_t)n * Dd + dc]);
            g_c[(size_t)n * Dd + dc] = cn;
            hout[(size_t)n * Dd + dc] = hn;
        }
    }
}

extern "C" void kernel_launch(void* const* d_in, const int* in_sizes, int n_in,
                              void* d_out, int out_size) {
    const float* f   = (const float*)d_in[0];
    const float* G   = (const float*)d_in[1];
    const float* Wih = (const float*)d_in[2];
    const float* Whh = (const float*)d_in[3];
    const float* bih = (const float*)d_in[4];
    const float* bhh = (const float*)d_in[5];
    float* out = (float*)d_out;

    k_init<<<(Nn * Dd) / 256, 256>>>(f);
    {
        float* Pp; cudaGetSymbolAddress((void**)&Pp, g_P);
        k_gemm<<<dim3(FD / 128, Nn / 64), 256>>>(f, 0, Wih, 1024, Pp, (const float*)0);
    }
    float* hwp; cudaGetSymbolAddress((void**)&hwp, g_hw);

    for (int s = 0; s < Kk; s++) {
        // merged: x<2 -> fused attn+r CTAs (rb = y*2+x), x>=2 -> h@W_hh^T tiles
        k_gemm<<<dim3(FD / 128 + 2, Nn / 64), 256>>>((const float*)0, s & 1, Whh, 512, hwp, G);
        k_gx<<<dim3(Dd / 32, Nn / 64), 256>>>(s & 1, Wih, bih, bhh, f, out, s == Kk - 1);
    }
}

// round 12
// speedup vs baseline: 1.2700x; 1.2700x over previous
#include <cuda_runtime.h>
#include <math.h>

#define Nn 8192
#define Kk 64
#define Dd 512
#define FD 2048   // 4*D

typedef unsigned long long u64t;

// ---- packed f32x2 ops (Blackwell FFMA2; each half = independent IEEE rn FMA) ----
#define PACKF2(d, lo, hi)  asm("mov.b64 %0, {%1, %2};" : "=l"(d) : "f"(lo), "f"(hi))
#define UNPACKF2(lo, hi, s) asm("mov.b64 {%0, %1}, %2;" : "=f"(lo), "=f"(hi) : "l"(s))
#define FMA2(d, a, b, c)   asm("fma.rn.f32x2 %0, %1, %2, %3;" : "=l"(d) : "l"(a), "l"(b), "l"(c))

// Scratch (allocation-free device globals)
__device__ float g_P[(size_t)Nn * FD];      // 64 MB: partial chain f@W_L^T (no biases)
__device__ float g_hw[(size_t)Nn * FD];     // 64 MB: h@W_hh^T per step
__device__ float g_h[2][(size_t)Nn * Dd];   // ping/pong h
__device__ float g_c[(size_t)Nn * Dd];      // cell state
__device__ float g_r[(size_t)Nn * Dd];      // r = a @ G

// ---- XLA EmitFastTanh f32 (verbatim) ----
__device__ __forceinline__ float tanh_xla(float x) {
    float ax = fabsf(x);
    float xc = fminf(fmaxf(x, -7.90531110763549805f), 7.90531110763549805f);
    float x2 = __fmul_rn(xc, xc);
    float p = -2.76076847742355e-16f;
    p = __fadd_rn(__fmul_rn(p, x2), 2.00018790482477e-13f);
    p = __fadd_rn(__fmul_rn(p, x2), -8.60467152213735e-11f);
    p = __fadd_rn(__fmul_rn(p, x2), 5.12229709037114e-08f);
    p = __fadd_rn(__fmul_rn(p, x2), 1.48572235717979e-05f);
    p = __fadd_rn(__fmul_rn(p, x2), 6.37261928875436e-04f);
    p = __fadd_rn(__fmul_rn(p, x2), 4.89352455891786e-03f);
    float num = __fmul_rn(xc, p);
    float q = 1.19825839466702e-06f;
    q = __fadd_rn(__fmul_rn(q, x2), 1.18534705686654e-04f);
    q = __fadd_rn(__fmul_rn(q, x2), 2.26843463243900e-03f);
    q = __fadd_rn(__fmul_rn(q, x2), 4.89352518554385e-03f);
    float r = __fdiv_rn(num, q);
    return (ax < 0.0004f) ? x : r;
}
__device__ __forceinline__ float sig_xla(float x) {
    return __fadd_rn(0.5f, __fmul_rn(0.5f, tanh_xla(__fmul_rn(0.5f, x))));
}

// ---------------- init: h0 = f, c = 0 ----------------
__global__ void k_init(const float* __restrict__ f) {
    int i = blockIdx.x * 256 + threadIdx.x;
    g_h[0][i] = f[i];
    g_c[i] = 0.f;
}

// Shared-memory overlay: gemm path 32768 B; attnr path 64*129*4 + 32*64*4 = 41216 B
#define SU_BYTES 41216

// ---- fused attention + r body: one CTA = 32 rows (rb in 0..255), verbatim R10 ----
__device__ __forceinline__ void attnr_body(char* su, int rb, const float* __restrict__ h,
                                           const float* __restrict__ G) {
    float* Gs = reinterpret_cast<float*>(su);                          // [64*129]
    float (*a2)[Kk] = reinterpret_cast<float(*)[Kk]>(su + Kk * 129 * 4);  // [32][64]
    const int tid = threadIdx.x;
    const int warp = tid >> 5, lane = tid & 31;
    const int n0 = rb * 32 + warp * 4;

    float acc[4][2];
#pragma unroll
    for (int r = 0; r < 4; r++) { acc[r][0] = 0.f; acc[r][1] = 0.f; }
    for (int ch = 0; ch < 4; ch++) {
        __syncthreads();
        for (int e = tid; e < Kk * 128; e += 256)
            Gs[(e >> 7) * 129 + (e & 127)] = G[(e >> 7) * Dd + ch * 128 + (e & 127)];
        __syncthreads();
#pragma unroll 2
        for (int d = 0; d < 128; d++) {
            float w0 = Gs[lane * 129 + d];
            float w1 = Gs[(lane + 32) * 129 + d];
#pragma unroll
            for (int r = 0; r < 4; r++) {
                float hv = h[(size_t)(n0 + r) * Dd + ch * 128 + d];
                acc[r][0] = fmaf(hv, w0, acc[r][0]);
                acc[r][1] = fmaf(hv, w1, acc[r][1]);
            }
        }
    }
#pragma unroll
    for (int r = 0; r < 4; r++) {
        float m = fmaxf(acc[r][0], acc[r][1]);
#pragma unroll
        for (int off = 16; off; off >>= 1) m = fmaxf(m, __shfl_xor_sync(0xffffffffu, m, off));
        float e0 = expf(acc[r][0] - m);
        float e1 = expf(acc[r][1] - m);
        float s = __fadd_rn(e0, e1);
#pragma unroll
        for (int off = 16; off; off >>= 1) s = __fadd_rn(s, __shfl_xor_sync(0xffffffffu, s, off));
        s = __shfl_sync(0xffffffffu, s, 0);
        a2[warp * 4 + r][lane]      = __fdiv_rn(e0, s);
        a2[warp * 4 + r][lane + 32] = __fdiv_rn(e1, s);
    }
    __syncthreads();

    float (*Gr)[128] = reinterpret_cast<float(*)[128]>(su);
    const int dthr = tid & 31, rgrp = tid >> 5;
    for (int ch = 0; ch < 4; ch++) {
        for (int e = tid; e < Kk * 128; e += 256)
            Gr[e >> 7][e & 127] = G[(size_t)(e >> 7) * Dd + ch * 128 + (e & 127)];
        __syncthreads();
        u64t acc2[4][2];
#pragma unroll
        for (int r = 0; r < 4; r++) { acc2[r][0] = 0ull; acc2[r][1] = 0ull; }
        for (int k = 0; k < Kk; k++) {
            u64t g2[2];
            *(uint4*)&g2[0] = *(const uint4*)&Gr[k][dthr * 4];
#pragma unroll
            for (int r = 0; r < 4; r++) {
                float av = a2[rgrp * 4 + r][k];
                u64t av2;
                PACKF2(av2, av, av);
                FMA2(acc2[r][0], av2, g2[0], acc2[r][0]);
                FMA2(acc2[r][1], av2, g2[1], acc2[r][1]);
            }
        }
#pragma unroll
        for (int r = 0; r < 4; r++) {
            float x0, x1, x2, x3;
            UNPACKF2(x0, x1, acc2[r][0]);
            UNPACKF2(x2, x3, acc2[r][1]);
            *(float4*)&g_r[(size_t)(rb * 32 + rgrp * 4 + r) * Dd + ch * 128 + dthr * 4] =
                make_float4(x0, x1, x2, x3);
        }
        __syncthreads();
    }
}

// ---------------- merged launch: gemm tiles + attnr CTAs ----------------
// G != null: grid (20, 64); x<4 -> attnr (rb = y*4+x), x>=4 -> gemm tile jb=(x-4)*128.
// G == null: pure gemm, grid (16, 64), jb = x*128 (P precompute).
// Warp tile remapped to 32 rows x 64 cols (lane grid 4x8) -> B footprint 256B/warp/k.
__global__ __launch_bounds__(256, 2) void k_gemm(const float* __restrict__ Aopt, int cur,
                                                 const float* __restrict__ B, long bstride,
                                                 float* __restrict__ C,
                                                 const float* __restrict__ G) {
    __shared__ __align__(16) char su[SU_BYTES];
    const float* __restrict__ A = Aopt ? Aopt : g_h[cur];
    int jb;
    if (G) {
        if (blockIdx.x < 4) { attnr_body(su, blockIdx.y * 4 + blockIdx.x, A, G); return; }
        jb = (blockIdx.x - 4) * 128;
    } else {
        jb = blockIdx.x * 128;
    }
    float (*As)[16][128] = reinterpret_cast<float(*)[16][128]>(su);
    float (*Bs)[16][128] = reinterpret_cast<float(*)[16][128]>(su + 16384);
    const int mb = blockIdx.y * 128;
    const int tid = threadIdx.x;
    // new warp/lane mapping: warp grid 4 (rows) x 2 (cols); lane grid 4 (rows) x 8 (cols)
    const int warp = tid >> 5, lane = tid & 31;
    const int wr = warp >> 1, wc = warp & 1;
    const int lr = lane & 3, lcx = lane >> 2;
    const int r0 = wr * 32 + lr * 8;     // 8 consecutive rows
    const int c0 = wc * 64 + lcx * 4;    // quad1 cols c0..c0+3, quad2 at c0+32
    const int lrow = tid >> 1, lk = (tid & 1) << 3;
    u64t acc2[8][4];
#pragma unroll
    for (int i = 0; i < 8; i++)
#pragma unroll
        for (int q = 0; q < 4; q++) acc2[i][q] = 0ull;

    const float* Arow = A + (size_t)(mb + lrow) * Dd + lk;
    const float* Brow = B + (size_t)(jb + lrow) * bstride + lk;

    float4 a0 = *(const float4*)(Arow), a1 = *(const float4*)(Arow + 4);
    float4 b0 = *(const float4*)(Brow), b1 = *(const float4*)(Brow + 4);
    As[0][lk + 0][lrow] = a0.x; As[0][lk + 1][lrow] = a0.y; As[0][lk + 2][lrow] = a0.z; As[0][lk + 3][lrow] = a0.w;
    As[0][lk + 4][lrow] = a1.x; As[0][lk + 5][lrow] = a1.y; As[0][lk + 6][lrow] = a1.z; As[0][lk + 7][lrow] = a1.w;
    Bs[0][lk + 0][lrow] = b0.x; Bs[0][lk + 1][lrow] = b0.y; Bs[0][lk + 2][lrow] = b0.z; Bs[0][lk + 3][lrow] = b0.w;
    Bs[0][lk + 4][lrow] = b1.x; Bs[0][lk + 5][lrow] = b1.y; Bs[0][lk + 6][lrow] = b1.z; Bs[0][lk + 7][lrow] = b1.w;
    __syncthreads();

    for (int kt = 0; kt < 32; kt++) {
        const int buf = kt & 1;
        if (kt < 31) {
            a0 = *(const float4*)(Arow + (kt + 1) * 16);
            a1 = *(const float4*)(Arow + (kt + 1) * 16 + 4);
            b0 = *(const float4*)(Brow + (kt + 1) * 16);
            b1 = *(const float4*)(Brow + (kt + 1) * 16 + 4);
        }
#pragma unroll
        for (int k = 0; k < 16; k++) {
            float ar[8];
            *(float4*)&ar[0] = *(const float4*)&As[buf][k][r0];
            *(float4*)&ar[4] = *(const float4*)&As[buf][k][r0 + 4];
            u64t ap[8], bp[4];
#pragma unroll
            for (int i = 0; i < 8; i++) PACKF2(ap[i], ar[i], ar[i]);
            *(uint4*)&bp[0] = *(const uint4*)&Bs[buf][k][c0];
            *(uint4*)&bp[2] = *(const uint4*)&Bs[buf][k][c0 + 32];
#pragma unroll
            for (int i = 0; i < 8; i++)
#pragma unroll
                for (int q = 0; q < 4; q++) FMA2(acc2[i][q], ap[i], bp[q], acc2[i][q]);
        }
        if (kt < 31) {
            const int nb = buf ^ 1;
            As[nb][lk + 0][lrow] = a0.x; As[nb][lk + 1][lrow] = a0.y; As[nb][lk + 2][lrow] = a0.z; As[nb][lk + 3][lrow] = a0.w;
            As[nb][lk + 4][lrow] = a1.x; As[nb][lk + 5][lrow] = a1.y; As[nb][lk + 6][lrow] = a1.z; As[nb][lk + 7][lrow] = a1.w;
            Bs[nb][lk + 0][lrow] = b0.x; Bs[nb][lk + 1][lrow] = b0.y; Bs[nb][lk + 2][lrow] = b0.z; Bs[nb][lk + 3][lrow] = b0.w;
            Bs[nb][lk + 4][lrow] = b1.x; Bs[nb][lk + 5][lrow] = b1.y; Bs[nb][lk + 6][lrow] = b1.z; Bs[nb][lk + 7][lrow] = b1.w;
            __syncthreads();
        }
    }
#pragma unroll
    for (int i = 0; i < 8; i++) {
        int n = mb + r0 + i;
#pragma unroll
        for (int q = 0; q < 2; q++) {
            float lo, hi;
            UNPACKF2(lo, hi, acc2[i][q]);
            *(float2*)&C[(size_t)n * FD + jb + c0 + q * 2] = make_float2(lo, hi);
        }
#pragma unroll
        for (int q = 2; q < 4; q++) {
            float lo, hi;
            UNPACKF2(lo, hi, acc2[i][q]);
            *(float2*)&C[(size_t)n * FD + jb + c0 + 32 + (q - 2) * 2] = make_float2(lo, hi);
        }
    }
}

// ---------------- x-chain GEMM (resumed from g_P) via FFMA2 + fused LSTM (verbatim R10) ----------------
__global__ __launch_bounds__(256, 2) void k_gx(int cur, const float* __restrict__ Wih,
        const float* __restrict__ bih, const float* __restrict__ bhh,
        const float* __restrict__ f, float* __restrict__ dout, int last) {
    __shared__ float As[2][16][128];
    __shared__ float Bs[2][16][128];
    float* __restrict__ hout = last ? dout : g_h[cur ^ 1];
    const int dcb = blockIdx.x * 32, mb = blockIdx.y * 128;
    const int tid = threadIdx.x, tx = tid & 15, ty = tid >> 4;
    const int lrow = tid >> 1, lk = (tid & 1) << 3;
    const size_t bj = (size_t)((lrow >> 5) * Dd + dcb + (lrow & 31));

    const float* Arow = g_r + (size_t)(mb + lrow) * Dd + lk;
    const float* Brow = Wih + bj * 1024 + 512 + lk;

    u64t acc2[8][4];
#pragma unroll
    for (int i = 0; i < 8; i++) {
        int n = mb + ty * 8 + i;
#pragma unroll
        for (int g = 0; g < 4; g++) {
            float2 v = *(const float2*)&g_P[(size_t)n * FD + g * Dd + dcb + tx * 2];
            PACKF2(acc2[i][g], v.x, v.y);
        }
    }

    float4 a0 = *(const float4*)(Arow), a1 = *(const float4*)(Arow + 4);
    float4 b0 = *(const float4*)(Brow), b1 = *(const float4*)(Brow + 4);
    As[0][lk + 0][lrow] = a0.x; As[0][lk + 1][lrow] = a0.y; As[0][lk + 2][lrow] = a0.z; As[0][lk + 3][lrow] = a0.w;
    As[0][lk + 4][lrow] = a1.x; As[0][lk + 5][lrow] = a1.y; As[0][lk + 6][lrow] = a1.z; As[0][lk + 7][lrow] = a1.w;
    Bs[0][lk + 0][lrow] = b0.x; Bs[0][lk + 1][lrow] = b0.y; Bs[0][lk + 2][lrow] = b0.z; Bs[0][lk + 3][lrow] = b0.w;
    Bs[0][lk + 4][lrow] = b1.x; Bs[0][lk + 5][lrow] = b1.y; Bs[0][lk + 6][lrow] = b1.z; Bs[0][lk + 7][lrow] = b1.w;
    __syncthreads();

    for (int kt = 0; kt < 32; kt++) {
        const int buf = kt & 1;
        if (kt < 31) {
            a0 = *(const float4*)(Arow + (kt + 1) * 16);
            a1 = *(const float4*)(Arow + (kt + 1) * 16 + 4);
            b0 = *(const float4*)(Brow + (kt + 1) * 16);
            b1 = *(const float4*)(Brow + (kt + 1) * 16 + 4);
        }
#pragma unroll
        for (int k = 0; k < 16; k++) {
            float ar[8];
            *(float4*)&ar[0] = *(const float4*)&As[buf][k][ty * 8];
            *(float4*)&ar[4] = *(const float4*)&As[buf][k][ty * 8 + 4];
            u64t ap[8], bp[4];
#pragma unroll
            for (int i = 0; i < 8; i++) PACKF2(ap[i], ar[i], ar[i]);
#pragma unroll
            for (int g = 0; g < 4; g++)
                bp[g] = *(const u64t*)&Bs[buf][k][g * 32 + tx * 2];
#pragma unroll
            for (int i = 0; i < 8; i++)
#pragma unroll
                for (int g = 0; g < 4; g++) FMA2(acc2[i][g], ap[i], bp[g], acc2[i][g]);
        }
        if (kt < 31) {
            const int nb = buf ^ 1;
            As[nb][lk + 0][lrow] = a0.x; As[nb][lk + 1][lrow] = a0.y; As[nb][lk + 2][lrow] = a0.z; As[nb][lk + 3][lrow] = a0.w;
            As[nb][lk + 4][lrow] = a1.x; As[nb][lk + 5][lrow] = a1.y; As[nb][lk + 6][lrow] = a1.z; As[nb][lk + 7][lrow] = a1.w;
            Bs[nb][lk + 0][lrow] = b0.x; Bs[nb][lk + 1][lrow] = b0.y; Bs[nb][lk + 2][lrow] = b0.z; Bs[nb][lk + 3][lrow] = b0.w;
            Bs[nb][lk + 4][lrow] = b1.x; Bs[nb][lk + 5][lrow] = b1.y; Bs[nb][lk + 6][lrow] = b1.z; Bs[nb][lk + 7][lrow] = b1.w;
            __syncthreads();
        }
    }

    // epilogue: ((x + b_ih) + hW) + b_hh, XLA pointwise (identical), write c / h
#pragma unroll
    for (int i = 0; i < 8; i++) {
        int n = mb + ty * 8 + i;
        const float* hwp = &g_hw[(size_t)n * FD];
        float ax[8];
#pragma unroll
        for (int g = 0; g < 4; g++) UNPACKF2(ax[g * 2], ax[g * 2 + 1], acc2[i][g]);
#pragma unroll
        for (int p = 0; p < 2; p++) {
            int dc = dcb + tx * 2 + p;
            float iv = __fadd_rn(__fadd_rn(__fadd_rn(ax[0 + p], bih[0 * Dd + dc]), hwp[0 * Dd + dc]), bhh[0 * Dd + dc]);
            float fv = __fadd_rn(__fadd_rn(__fadd_rn(ax[2 + p], bih[1 * Dd + dc]), hwp[1 * Dd + dc]), bhh[1 * Dd + dc]);
            float gv = __fadd_rn(__fadd_rn(__fadd_rn(ax[4 + p], bih[2 * Dd + dc]), hwp[2 * Dd + dc]), bhh[2 * Dd + dc]);
            float ov = __fadd_rn(__fadd_rn(__fadd_rn(ax[6 + p], bih[3 * Dd + dc]), hwp[3 * Dd + dc]), bhh[3 * Dd + dc]);
            float co = g_c[(size_t)n * Dd + dc];
            float cn = __fadd_rn(__fmul_rn(sig_xla(fv), co), __fmul_rn(sig_xla(iv), tanh_xla(gv)));
            float hn = __fadd_rn(__fmul_rn(sig_xla(ov), tanh_xla(cn)), f[(size_t)n * Dd + dc]);
            g_c[(size_t)n * Dd + dc] = cn;
            hout[(size_t)n * Dd + dc] = hn;
        }
    }
}

extern "C" void kernel_launch(void* const* d_in, const int* in_sizes, int n_in,
                              void* d_out, int out_size) {
    const float* f   = (const float*)d_in[0];
    const float* G   = (const float*)d_in[1];
    const float* Wih = (const float*)d_in[2];
    const float* Whh = (const float*)d_in[3];
    const float* bih = (const float*)d_in[4];
    const float* bhh = (const float*)d_in[5];
    float* out = (float*)d_out;

    k_init<<<(Nn * Dd) / 256, 256>>>(f);
    {
        float* Pp; cudaGetSymbolAddress((void**)&Pp, g_P);
        k_gemm<<<dim3(FD / 128, Nn / 128), 256>>>(f, 0, Wih, 1024, Pp, (const float*)0);
    }
    float* hwp; cudaGetSymbolAddress((void**)&hwp, g_hw);

    for (int s = 0; s < Kk; s++) {
        // merged: x<4 -> fused attn+r CTAs (rb = y*4+x), x>=4 -> h@W_hh^T tiles
        k_gemm<<<dim3(FD / 128 + 4, Nn / 128), 256>>>((const float*)0, s & 1, Whh, 512, hwp, G);
        k_gx<<<dim3(Dd / 32, Nn / 128), 256>>>(s & 1, Wih, bih, bhh, f, out, s == Kk - 1);
    }
}

// round 13
// speedup vs baseline: 1.2904x; 1.0161x over previous
#include <cuda_runtime.h>
#include <math.h>

#define Nn 8192
#define Kk 64
#define Dd 512
#define FD 2048   // 4*D

typedef unsigned long long u64t;

// ---- packed f32x2 ops (Blackwell FFMA2; each half = independent IEEE rn FMA) ----
#define PACKF2(d, lo, hi)  asm("mov.b64 %0, {%1, %2};" : "=l"(d) : "f"(lo), "f"(hi))
#define UNPACKF2(lo, hi, s) asm("mov.b64 {%0, %1}, %2;" : "=f"(lo), "=f"(hi) : "l"(s))
#define FMA2(d, a, b, c)   asm("fma.rn.f32x2 %0, %1, %2, %3;" : "=l"(d) : "l"(a), "l"(b), "l"(c))

// Scratch (allocation-free device globals)
__device__ float g_P[(size_t)Nn * FD];      // 64 MB: partial chain f@W_L^T (no biases)
__device__ float g_hw[(size_t)Nn * FD];     // 64 MB: h@W_hh^T per step
__device__ float g_h[2][(size_t)Nn * Dd];   // ping/pong h
__device__ float g_c[(size_t)Nn * Dd];      // cell state
__device__ float g_r[(size_t)Nn * Dd];      // r = a @ G

// ---- XLA EmitFastTanh f32 (verbatim) ----
__device__ __forceinline__ float tanh_xla(float x) {
    float ax = fabsf(x);
    float xc = fminf(fmaxf(x, -7.90531110763549805f), 7.90531110763549805f);
    float x2 = __fmul_rn(xc, xc);
    float p = -2.76076847742355e-16f;
    p = __fadd_rn(__fmul_rn(p, x2), 2.00018790482477e-13f);
    p = __fadd_rn(__fmul_rn(p, x2), -8.60467152213735e-11f);
    p = __fadd_rn(__fmul_rn(p, x2), 5.12229709037114e-08f);
    p = __fadd_rn(__fmul_rn(p, x2), 1.48572235717979e-05f);
    p = __fadd_rn(__fmul_rn(p, x2), 6.37261928875436e-04f);
    p = __fadd_rn(__fmul_rn(p, x2), 4.89352455891786e-03f);
    float num = __fmul_rn(xc, p);
    float q = 1.19825839466702e-06f;
    q = __fadd_rn(__fmul_rn(q, x2), 1.18534705686654e-04f);
    q = __fadd_rn(__fmul_rn(q, x2), 2.26843463243900e-03f);
    q = __fadd_rn(__fmul_rn(q, x2), 4.89352518554385e-03f);
    float r = __fdiv_rn(num, q);
    return (ax < 0.0004f) ? x : r;
}
__device__ __forceinline__ float sig_xla(float x) {
    return __fadd_rn(0.5f, __fmul_rn(0.5f, tanh_xla(__fmul_rn(0.5f, x))));
}

// ---------------- init: h0 = f, c = 0 ----------------
__global__ void k_init(const float* __restrict__ f) {
    int i = blockIdx.x * 256 + threadIdx.x;
    g_h[0][i] = f[i];
    g_c[i] = 0.f;
}

// Shared-memory overlay: gemm path 32768 B; attnr path 64*129*4 + 32*64*4 = 41216 B
#define SU_BYTES 41216

// ---- fused attention + r body: one CTA = 32 rows (rb in 0..255), verbatim ----
__device__ __forceinline__ void attnr_body(char* su, int rb, const float* __restrict__ h,
                                           const float* __restrict__ G) {
    float* Gs = reinterpret_cast<float*>(su);                          // [64*129]
    float (*a2)[Kk] = reinterpret_cast<float(*)[Kk]>(su + Kk * 129 * 4);  // [32][64]
    const int tid = threadIdx.x;
    const int warp = tid >> 5, lane = tid & 31;
    const int n0 = rb * 32 + warp * 4;

    float acc[4][2];
#pragma unroll
    for (int r = 0; r < 4; r++) { acc[r][0] = 0.f; acc[r][1] = 0.f; }
    for (int ch = 0; ch < 4; ch++) {
        __syncthreads();
        for (int e = tid; e < Kk * 128; e += 256)
            Gs[(e >> 7) * 129 + (e & 127)] = G[(e >> 7) * Dd + ch * 128 + (e & 127)];
        __syncthreads();
#pragma unroll 2
        for (int d = 0; d < 128; d++) {
            float w0 = Gs[lane * 129 + d];
            float w1 = Gs[(lane + 32) * 129 + d];
#pragma unroll
            for (int r = 0; r < 4; r++) {
                float hv = h[(size_t)(n0 + r) * Dd + ch * 128 + d];
                acc[r][0] = fmaf(hv, w0, acc[r][0]);
                acc[r][1] = fmaf(hv, w1, acc[r][1]);
            }
        }
    }
#pragma unroll
    for (int r = 0; r < 4; r++) {
        float m = fmaxf(acc[r][0], acc[r][1]);
#pragma unroll
        for (int off = 16; off; off >>= 1) m = fmaxf(m, __shfl_xor_sync(0xffffffffu, m, off));
        float e0 = expf(acc[r][0] - m);
        float e1 = expf(acc[r][1] - m);
        float s = __fadd_rn(e0, e1);
#pragma unroll
        for (int off = 16; off; off >>= 1) s = __fadd_rn(s, __shfl_xor_sync(0xffffffffu, s, off));
        s = __shfl_sync(0xffffffffu, s, 0);
        a2[warp * 4 + r][lane]      = __fdiv_rn(e0, s);
        a2[warp * 4 + r][lane + 32] = __fdiv_rn(e1, s);
    }
    __syncthreads();

    float (*Gr)[128] = reinterpret_cast<float(*)[128]>(su);
    const int dthr = tid & 31, rgrp = tid >> 5;
    for (int ch = 0; ch < 4; ch++) {
        for (int e = tid; e < Kk * 128; e += 256)
            Gr[e >> 7][e & 127] = G[(size_t)(e >> 7) * Dd + ch * 128 + (e & 127)];
        __syncthreads();
        u64t acc2[4][2];
#pragma unroll
        for (int r = 0; r < 4; r++) { acc2[r][0] = 0ull; acc2[r][1] = 0ull; }
        for (int k = 0; k < Kk; k++) {
            u64t g2[2];
            *(uint4*)&g2[0] = *(const uint4*)&Gr[k][dthr * 4];
#pragma unroll
            for (int r = 0; r < 4; r++) {
                float av = a2[rgrp * 4 + r][k];
                u64t av2;
                PACKF2(av2, av, av);
                FMA2(acc2[r][0], av2, g2[0], acc2[r][0]);
                FMA2(acc2[r][1], av2, g2[1], acc2[r][1]);
            }
        }
#pragma unroll
        for (int r = 0; r < 4; r++) {
            float x0, x1, x2, x3;
            UNPACKF2(x0, x1, acc2[r][0]);
            UNPACKF2(x2, x3, acc2[r][1]);
            *(float4*)&g_r[(size_t)(rb * 32 + rgrp * 4 + r) * Dd + ch * 128 + dthr * 4] =
                make_float4(x0, x1, x2, x3);
        }
        __syncthreads();
    }
}

// ---------------- merged launch: gemm tiles + attnr CTAs ----------------
__global__ __launch_bounds__(256, 2) void k_gemm(const float* __restrict__ Aopt, int cur,
                                                 const float* __restrict__ B, long bstride,
                                                 float* __restrict__ C,
                                                 const float* __restrict__ G) {
    __shared__ __align__(16) char su[SU_BYTES];
    const float* __restrict__ A = Aopt ? Aopt : g_h[cur];
    int jb;
    if (G) {
        if (blockIdx.x < 4) { attnr_body(su, blockIdx.y * 4 + blockIdx.x, A, G); return; }
        jb = (blockIdx.x - 4) * 128;
    } else {
        jb = blockIdx.x * 128;
    }
    float (*As)[16][128] = reinterpret_cast<float(*)[16][128]>(su);
    float (*Bs)[16][128] = reinterpret_cast<float(*)[16][128]>(su + 16384);
    const int mb = blockIdx.y * 128;
    const int tid = threadIdx.x;
    const int warp = tid >> 5, lane = tid & 31;
    const int wr = warp >> 1, wc = warp & 1;
    const int lr = lane & 3, lcx = lane >> 2;
    const int r0 = wr * 32 + lr * 8;
    const int c0 = wc * 64 + lcx * 4;
    const int lrow = tid >> 1, lk = (tid & 1) << 3;
    u64t acc2[8][4];
#pragma unroll
    for (int i = 0; i < 8; i++)
#pragma unroll
        for (int q = 0; q < 4; q++) acc2[i][q] = 0ull;

    const float* Arow = A + (size_t)(mb + lrow) * Dd + lk;
    const float* Brow = B + (size_t)(jb + lrow) * bstride + lk;

    float4 a0 = *(const float4*)(Arow), a1 = *(const float4*)(Arow + 4);
    float4 b0 = *(const float4*)(Brow), b1 = *(const float4*)(Brow + 4);
    As[0][lk + 0][lrow] = a0.x; As[0][lk + 1][lrow] = a0.y; As[0][lk + 2][lrow] = a0.z; As[0][lk + 3][lrow] = a0.w;
    As[0][lk + 4][lrow] = a1.x; As[0][lk + 5][lrow] = a1.y; As[0][lk + 6][lrow] = a1.z; As[0][lk + 7][lrow] = a1.w;
    Bs[0][lk + 0][lrow] = b0.x; Bs[0][lk + 1][lrow] = b0.y; Bs[0][lk + 2][lrow] = b0.z; Bs[0][lk + 3][lrow] = b0.w;
    Bs[0][lk + 4][lrow] = b1.x; Bs[0][lk + 5][lrow] = b1.y; Bs[0][lk + 6][lrow] = b1.z; Bs[0][lk + 7][lrow] = b1.w;
    __syncthreads();

    for (int kt = 0; kt < 32; kt++) {
        const int buf = kt & 1;
        if (kt < 31) {
            a0 = *(const float4*)(Arow + (kt + 1) * 16);
            a1 = *(const float4*)(Arow + (kt + 1) * 16 + 4);
            b0 = *(const float4*)(Brow + (kt + 1) * 16);
            b1 = *(const float4*)(Brow + (kt + 1) * 16 + 4);
        }
#pragma unroll
        for (int k = 0; k < 16; k++) {
            float ar[8];
            *(float4*)&ar[0] = *(const float4*)&As[buf][k][r0];
            *(float4*)&ar[4] = *(const float4*)&As[buf][k][r0 + 4];
            u64t ap[8], bp[4];
#pragma unroll
            for (int i = 0; i < 8; i++) PACKF2(ap[i], ar[i], ar[i]);
            *(uint4*)&bp[0] = *(const uint4*)&Bs[buf][k][c0];
            *(uint4*)&bp[2] = *(const uint4*)&Bs[buf][k][c0 + 32];
#pragma unroll
            for (int i = 0; i < 8; i++)
#pragma unroll
                for (int q = 0; q < 4; q++) FMA2(acc2[i][q], ap[i], bp[q], acc2[i][q]);
        }
        if (kt < 31) {
            const int nb = buf ^ 1;
            As[nb][lk + 0][lrow] = a0.x; As[nb][lk + 1][lrow] = a0.y; As[nb][lk + 2][lrow] = a0.z; As[nb][lk + 3][lrow] = a0.w;
            As[nb][lk + 4][lrow] = a1.x; As[nb][lk + 5][lrow] = a1.y; As[nb][lk + 6][lrow] = a1.z; As[nb][lk + 7][lrow] = a1.w;
            Bs[nb][lk + 0][lrow] = b0.x; Bs[nb][lk + 1][lrow] = b0.y; Bs[nb][lk + 2][lrow] = b0.z; Bs[nb][lk + 3][lrow] = b0.w;
            Bs[nb][lk + 4][lrow] = b1.x; Bs[nb][lk + 5][lrow] = b1.y; Bs[nb][lk + 6][lrow] = b1.z; Bs[nb][lk + 7][lrow] = b1.w;
            __syncthreads();
        }
    }
    // vectorized store: quads are contiguous -> 2x STG.128 per row
#pragma unroll
    for (int i = 0; i < 8; i++) {
        int n = mb + r0 + i;
        float x0, x1, x2, x3;
        UNPACKF2(x0, x1, acc2[i][0]);
        UNPACKF2(x2, x3, acc2[i][1]);
        *(float4*)&C[(size_t)n * FD + jb + c0] = make_float4(x0, x1, x2, x3);
        UNPACKF2(x0, x1, acc2[i][2]);
        UNPACKF2(x2, x3, acc2[i][3]);
        *(float4*)&C[(size_t)n * FD + jb + c0 + 32] = make_float4(x0, x1, x2, x3);
    }
}

// ---------------- x-chain GEMM (resumed from g_P) via FFMA2 + fused LSTM ----------------
__global__ __launch_bounds__(256, 2) void k_gx(int cur, const float* __restrict__ Wih,
        const float* __restrict__ bih, const float* __restrict__ bhh,
        const float* __restrict__ f, float* __restrict__ dout, int last) {
    __shared__ float As[2][16][128];
    __shared__ float Bs[2][16][128];
    float* __restrict__ hout = last ? dout : g_h[cur ^ 1];
    const int dcb = blockIdx.x * 32, mb = blockIdx.y * 128;
    const int tid = threadIdx.x, tx = tid & 15, ty = tid >> 4;
    const int lrow = tid >> 1, lk = (tid & 1) << 3;
    const size_t bj = (size_t)((lrow >> 5) * Dd + dcb + (lrow & 31));

    const float* Arow = g_r + (size_t)(mb + lrow) * Dd + lk;
    const float* Brow = Wih + bj * 1024 + 512 + lk;

    u64t acc2[8][4];
#pragma unroll
    for (int i = 0; i < 8; i++) {
        int n = mb + ty * 8 + i;
#pragma unroll
        for (int g = 0; g < 4; g++) {
            float2 v = *(const float2*)&g_P[(size_t)n * FD + g * Dd + dcb + tx * 2];
            PACKF2(acc2[i][g], v.x, v.y);
        }
    }

    float4 a0 = *(const float4*)(Arow), a1 = *(const float4*)(Arow + 4);
    float4 b0 = *(const float4*)(Brow), b1 = *(const float4*)(Brow + 4);
    As[0][lk + 0][lrow] = a0.x; As[0][lk + 1][lrow] = a0.y; As[0][lk + 2][lrow] = a0.z; As[0][lk + 3][lrow] = a0.w;
    As[0][lk + 4][lrow] = a1.x; As[0][lk + 5][lrow] = a1.y; As[0][lk + 6][lrow] = a1.z; As[0][lk + 7][lrow] = a1.w;
    Bs[0][lk + 0][lrow] = b0.x; Bs[0][lk + 1][lrow] = b0.y; Bs[0][lk + 2][lrow] = b0.z; Bs[0][lk + 3][lrow] = b0.w;
    Bs[0][lk + 4][lrow] = b1.x; Bs[0][lk + 5][lrow] = b1.y; Bs[0][lk + 6][lrow] = b1.z; Bs[0][lk + 7][lrow] = b1.w;
    __syncthreads();

    for (int kt = 0; kt < 32; kt++) {
        const int buf = kt & 1;
        if (kt < 31) {
            a0 = *(const float4*)(Arow + (kt + 1) * 16);
            a1 = *(const float4*)(Arow + (kt + 1) * 16 + 4);
            b0 = *(const float4*)(Brow + (kt + 1) * 16);
            b1 = *(const float4*)(Brow + (kt + 1) * 16 + 4);
        }
#pragma unroll
        for (int k = 0; k < 16; k++) {
            float ar[8];
            *(float4*)&ar[0] = *(const float4*)&As[buf][k][ty * 8];
            *(float4*)&ar[4] = *(const float4*)&As[buf][k][ty * 8 + 4];
            u64t ap[8], bp[4];
#pragma unroll
            for (int i = 0; i < 8; i++) PACKF2(ap[i], ar[i], ar[i]);
#pragma unroll
            for (int g = 0; g < 4; g++)
                bp[g] = *(const u64t*)&Bs[buf][k][g * 32 + tx * 2];
#pragma unroll
            for (int i = 0; i < 8; i++)
#pragma unroll
                for (int g = 0; g < 4; g++) FMA2(acc2[i][g], ap[i], bp[g], acc2[i][g]);
        }
        if (kt < 31) {
            const int nb = buf ^ 1;
            As[nb][lk + 0][lrow] = a0.x; As[nb][lk + 1][lrow] = a0.y; As[nb][lk + 2][lrow] = a0.z; As[nb][lk + 3][lrow] = a0.w;
            As[nb][lk + 4][lrow] = a1.x; As[nb][lk + 5][lrow] = a1.y; As[nb][lk + 6][lrow] = a1.z; As[nb][lk + 7][lrow] = a1.w;
            Bs[nb][lk + 0][lrow] = b0.x; Bs[nb][lk + 1][lrow] = b0.y; Bs[nb][lk + 2][lrow] = b0.z; Bs[nb][lk + 3][lrow] = b0.w;
            Bs[nb][lk + 4][lrow] = b1.x; Bs[nb][lk + 5][lrow] = b1.y; Bs[nb][lk + 6][lrow] = b1.z; Bs[nb][lk + 7][lrow] = b1.w;
            __syncthreads();
        }
    }

    // epilogue: ((x + b_ih) + hW) + b_hh, XLA pointwise (identical arithmetic),
    // vectorized: biases hoisted out of the row loop; hw/c/f/out as float2.
    const int dc0 = dcb + tx * 2;
    float2 bi2[4], bh2[4];
#pragma unroll
    for (int g = 0; g < 4; g++) {
        bi2[g] = *(const float2*)&bih[g * Dd + dc0];
        bh2[g] = *(const float2*)&bhh[g * Dd + dc0];
    }
#pragma unroll
    for (int i = 0; i < 8; i++) {
        int n = mb + ty * 8 + i;
        float2 hw2[4];
#pragma unroll
        for (int g = 0; g < 4; g++)
            hw2[g] = *(const float2*)&g_hw[(size_t)n * FD + g * Dd + dc0];
        float2 co2 = *(const float2*)&g_c[(size_t)n * Dd + dc0];
        float2 ff2 = *(const float2*)&f[(size_t)n * Dd + dc0];
        float ax[8];
#pragma unroll
        for (int g = 0; g < 4; g++) UNPACKF2(ax[g * 2], ax[g * 2 + 1], acc2[i][g]);

        float iv0 = __fadd_rn(__fadd_rn(__fadd_rn(ax[0], bi2[0].x), hw2[0].x), bh2[0].x);
        float fv0 = __fadd_rn(__fadd_rn(__fadd_rn(ax[2], bi2[1].x), hw2[1].x), bh2[1].x);
        float gv0 = __fadd_rn(__fadd_rn(__fadd_rn(ax[4], bi2[2].x), hw2[2].x), bh2[2].x);
        float ov0 = __fadd_rn(__fadd_rn(__fadd_rn(ax[6], bi2[3].x), hw2[3].x), bh2[3].x);
        float cn0 = __fadd_rn(__fmul_rn(sig_xla(fv0), co2.x), __fmul_rn(sig_xla(iv0), tanh_xla(gv0)));
        float hn0 = __fadd_rn(__fmul_rn(sig_xla(ov0), tanh_xla(cn0)), ff2.x);

        float iv1 = __fadd_rn(__fadd_rn(__fadd_rn(ax[1], bi2[0].y), hw2[0].y), bh2[0].y);
        float fv1 = __fadd_rn(__fadd_rn(__fadd_rn(ax[3], bi2[1].y), hw2[1].y), bh2[1].y);
        float gv1 = __fadd_rn(__fadd_rn(__fadd_rn(ax[5], bi2[2].y), hw2[2].y), bh2[2].y);
        float ov1 = __fadd_rn(__fadd_rn(__fadd_rn(ax[7], bi2[3].y), hw2[3].y), bh2[3].y);
        float cn1 = __fadd_rn(__fmul_rn(sig_xla(fv1), co2.y), __fmul_rn(sig_xla(iv1), tanh_xla(gv1)));
        float hn1 = __fadd_rn(__fmul_rn(sig_xla(ov1), tanh_xla(cn1)), ff2.y);

        *(float2*)&g_c[(size_t)n * Dd + dc0] = make_float2(cn0, cn1);
        *(float2*)&hout[(size_t)n * Dd + dc0] = make_float2(hn0, hn1);
    }
}

extern "C" void kernel_launch(void* const* d_in, const int* in_sizes, int n_in,
                              void* d_out, int out_size) {
    const float* f   = (const float*)d_in[0];
    const float* G   = (const float*)d_in[1];
    const float* Wih = (const float*)d_in[2];
    const float* Whh = (const float*)d_in[3];
    const float* bih = (const float*)d_in[4];
    const float* bhh = (const float*)d_in[5];
    float* out = (float*)d_out;

    k_init<<<(Nn * Dd) / 256, 256>>>(f);
    {
        float* Pp; cudaGetSymbolAddress((void**)&Pp, g_P);
        k_gemm<<<dim3(FD / 128, Nn / 128), 256>>>(f, 0, Wih, 1024, Pp, (const float*)0);
    }
    float* hwp; cudaGetSymbolAddress((void**)&hwp, g_hw);

    for (int s = 0; s < Kk; s++) {
        // merged: x<4 -> fused attn+r CTAs (rb = y*4+x), x>=4 -> h@W_hh^T tiles
        k_gemm<<<dim3(FD / 128 + 4, Nn / 128), 256>>>((const float*)0, s & 1, Whh, 512, hwp, G);
        k_gx<<<dim3(Dd / 32, Nn / 128), 256>>>(s & 1, Wih, bih, bhh, f, out, s == Kk - 1);
    }
}